// round 16
// baseline (speedup 1.0000x reference)
#include <cuda_runtime.h>

#define FULLMASK 0xffffffffu

constexpr int B = 64;
constexpr int L = 512;
constexpr int R = 1024;
constexpr int A = 14;
constexpr float EPSV = 1e-12f;
constexpr float CUT2 = 25.0f;     // CUTOFF^2

constexpr int LIG_BLOCKS_PER_B = 4;                       // each does 7 off-diag + 2 diag tiles
constexpr int LIG_BLOCKS = B * LIG_BLOCKS_PER_B;          // 256
constexpr int SC_GROUPS_PER_BLOCK = 64;                   // 8 warps x 8 groups
constexpr int SC_BLOCKS = (B * R) / SC_GROUPS_PER_BLOCK;  // 1024
constexpr int GRID = LIG_BLOCKS + SC_BLOCKS;              // 1280
constexpr int NSLOT = 32;

// -------- persistent scratch (zeroed at load; finalizer re-zeros each run) --------
__device__ float g_lig_num[B];
__device__ float g_lig_den[B];
__device__ float g_lig_se[B];
__device__ float g_lig_cnt[B];
__device__ float g_slots[4][NSLOT];
__device__ unsigned int g_ticket;

// off-diagonal tile pair table: (a<<4)|b for 0<=a<b<8, 28 entries
__constant__ unsigned char c_tpairs[28] = {
    0x01,0x02,0x03,0x04,0x05,0x06,0x07,
    0x12,0x13,0x14,0x15,0x16,0x17,
    0x23,0x24,0x25,0x26,0x27,
    0x34,0x35,0x36,0x37,
    0x45,0x46,0x47,
    0x56,0x57,
    0x67
};

typedef unsigned long long u64;

__device__ __forceinline__ float fast_sqrt(float x) {
    float r;
    asm("sqrt.approx.f32 %0, %1;" : "=f"(r) : "f"(x));
    return r;
}
__device__ __forceinline__ u64 f2x_pack(float lo, float hi) {
    u64 r; asm("mov.b64 %0, {%1, %2};" : "=l"(r) : "f"(lo), "f"(hi)); return r;
}
__device__ __forceinline__ void f2x_unpack(u64 v, float& lo, float& hi) {
    asm("mov.b64 {%0, %1}, %2;" : "=f"(lo), "=f"(hi) : "l"(v));
}
__device__ __forceinline__ u64 f2x_add(u64 a, u64 b) {
    u64 r; asm("add.rn.f32x2 %0, %1, %2;" : "=l"(r) : "l"(a), "l"(b)); return r;
}
__device__ __forceinline__ u64 f2x_mul(u64 a, u64 b) {
    u64 r; asm("mul.rn.f32x2 %0, %1, %2;" : "=l"(r) : "l"(a), "l"(b)); return r;
}
__device__ __forceinline__ u64 f2x_fma(u64 a, u64 b, u64 c) {
    u64 r; asm("fma.rn.f32x2 %0, %1, %2, %3;" : "=l"(r) : "l"(a), "l"(b), "l"(c)); return r;
}

// packed epilogue: acc = (psq, tsq); accumulate (pd-td)^2 when tsq <= CUT2
// (tsq==0 impossible: i!=j structurally, masked targets pushed far apart)
__device__ __forceinline__ void pair_epi(u64 acc, float& num, float& den) {
    float psq, tsq;
    f2x_unpack(acc, psq, tsq);
    float pe = fmaxf(psq, EPSV);
    float v = (pe + tsq) - 2.f * fast_sqrt(pe * tsq);
    if (tsq <= CUT2) { num += v; den += 1.f; }
}

__global__ void __launch_bounds__(256, 6) fused_kernel(
    const float* __restrict__ lp, const float* __restrict__ lt,
    const float* __restrict__ scp, const float* __restrict__ sct,
    const unsigned int* __restrict__ lm, const unsigned int* __restrict__ am,
    float* __restrict__ out, int out_size)
{
    // packed layout: s_a[j] = (px, tx, py, ty), s_b[j] = (pz, tz, |p|^2, |t|^2)
    __shared__ float4 s_a[L];     // 8 KB
    __shared__ float4 s_b[L];     // 8 KB
    __shared__ float4 wr[8];
    __shared__ float bacc[4];
    __shared__ unsigned int s_islast;
    __shared__ float fin[3][2];
    __shared__ float sl[4];

    const int t = threadIdx.x;
    const int bid = blockIdx.x;
    const int lane = t & 31;
    const int w = t >> 5;
    const u64 NEG2 = f2x_pack(-2.f, -2.f);

    if (bid < LIG_BLOCKS) {
        // ======================= ligand =======================
        const int b = bid >> 2;
        const int r = bid & 3;
        const float* P = lp + (size_t)b * L * 3;
        const float* T = lt + (size_t)b * L * 3;
        const unsigned int* M = lm + (size_t)b * L;

        float num = 0.f, den = 0.f, se = 0.f, cnt = 0.f;

        // fill all 512 points once (packed layout); r==0 also does the coord MSE
        for (int j = t; j < L; j += 256) {
            float px = P[j*3+0], py = P[j*3+1], pz = P[j*3+2];
            float tx = T[j*3+0], ty = T[j*3+1], tz = T[j*3+2];
            bool m = (M[j] != 0u);
            if (r == 0 && m) {
                float dx = px - tx, dy = py - ty, dz = pz - tz;
                se  += dx*dx + dy*dy + dz*dz;
                cnt += 1.f;
            }
            if (!m) tx += 1e4f + 64.f * (float)j;   // push invalid targets apart
            float pw = px*px + py*py + pz*pz;
            float tw = tx*tx + ty*ty + tz*tz;
            s_a[j] = make_float4(px, tx, py, ty);
            s_b[j] = make_float4(pz, tz, pw, tw);
        }
        __syncthreads();   // smem read-only from here on

        const ulonglong2* sa2 = (const ulonglong2*)s_a;
        const ulonglong2* sb2 = (const ulonglong2*)s_b;

        // ---- 7 off-diagonal 64x64 tile combos (2i x 8j, broadcast j, packed math) ----
        #pragma unroll 1
        for (int c = 7*r; c < 7*r + 7; ++c) {
            const int code = c_tpairs[c];
            const int ta = code >> 4, tb = code & 15;
            const int ia = ta*64 + lane;
            ulonglong2 a0 = sa2[ia],      b0 = sb2[ia];
            ulonglong2 a1 = sa2[ia + 32], b1 = sb2[ia + 32];
            const u64 ix0 = f2x_mul(a0.x, NEG2), iy0 = f2x_mul(a0.y, NEG2),
                      iz0 = f2x_mul(b0.x, NEG2), iw0 = b0.y;
            const u64 ix1 = f2x_mul(a1.x, NEG2), iy1 = f2x_mul(a1.y, NEG2),
                      iz1 = f2x_mul(b1.x, NEG2), iw1 = b1.y;
            const int jb = tb*64 + w;       // warp-uniform j -> broadcast LDS
            #pragma unroll
            for (int it = 0; it < 8; ++it) {
                ulonglong2 aj = sa2[jb + 8*it];
                ulonglong2 bj = sb2[jb + 8*it];
                u64 acc0 = f2x_add(iw0, bj.y);
                acc0 = f2x_fma(ix0, aj.x, acc0);
                acc0 = f2x_fma(iy0, aj.y, acc0);
                acc0 = f2x_fma(iz0, bj.x, acc0);
                pair_epi(acc0, num, den);
                u64 acc1 = f2x_add(iw1, bj.y);
                acc1 = f2x_fma(ix1, aj.x, acc1);
                acc1 = f2x_fma(iy1, aj.y, acc1);
                acc1 = f2x_fma(iz1, bj.x, acc1);
                pair_epi(acc1, num, den);
            }
        }

        // ---- 2 diagonal tiles: round-robin within 64 (packed math) ----
        #pragma unroll 1
        for (int dt_ = 2*r; dt_ < 2*r + 2; ++dt_) {
            const int base = dt_ * 64;
            const int il   = t & 63;
            const int off  = t >> 6;
            ulonglong2 ai = sa2[base + il], bi = sb2[base + il];
            const u64 ix = f2x_mul(ai.x, NEG2), iy = f2x_mul(ai.y, NEG2),
                      iz = f2x_mul(bi.x, NEG2), iw = bi.y;
            #pragma unroll
            for (int k = 1 + off; k <= 32; k += 4) {
                if (k == 32 && il >= 32) break;
                int j = base + ((il + k) & 63);
                ulonglong2 aj = sa2[j];
                ulonglong2 bj = sb2[j];
                u64 acc = f2x_add(iw, bj.y);
                acc = f2x_fma(ix, aj.x, acc);
                acc = f2x_fma(iy, aj.y, acc);
                acc = f2x_fma(iz, bj.x, acc);
                pair_epi(acc, num, den);
            }
        }

        // block reduce 4 vars -> per-batch atomics
        #pragma unroll
        for (int s = 16; s > 0; s >>= 1) {
            num += __shfl_down_sync(FULLMASK, num, s);
            den += __shfl_down_sync(FULLMASK, den, s);
            se  += __shfl_down_sync(FULLMASK, se,  s);
            cnt += __shfl_down_sync(FULLMASK, cnt, s);
        }
        if (lane == 0) wr[w] = make_float4(num, den, se, cnt);
        __syncthreads();
        if (t < 8) {
            float4 v4 = wr[t];
            float a0 = v4.x, a1 = v4.y, a2 = v4.z, a3 = v4.w;
            #pragma unroll
            for (int s = 4; s > 0; s >>= 1) {
                a0 += __shfl_down_sync(0xffu, a0, s);
                a1 += __shfl_down_sync(0xffu, a1, s);
                a2 += __shfl_down_sync(0xffu, a2, s);
                a3 += __shfl_down_sync(0xffu, a3, s);
            }
            if (t == 0) {
                atomicAdd(&g_lig_num[b], a0);
                atomicAdd(&g_lig_den[b], a1);
                atomicAdd(&g_lig_se[b],  a2);
                atomicAdd(&g_lig_cnt[b], a3);
            }
        }
    } else {
        // ======================= sidechain (packed shfl-based, 8 groups/warp) =======================
        if (t < 4) bacc[t] = 0.f;
        __syncthreads();

        const int h = (lane >> 4);          // half-warp id
        const int a = lane & 15;            // atom slot
        const bool av = a < A;
        const unsigned int g0 = (unsigned int)(bid - LIG_BLOCKS) * SC_GROUPS_PER_BLOCK + w * 8 + h;

        // base pointers computed once; advanced by constant strides per iteration
        const float* Pg = scp + (size_t)g0 * (A*3) + a*3;
        const float* Tg = sct + (size_t)g0 * (A*3) + a*3;
        const unsigned int* Ag = am + (size_t)g0 * A + a;

        float acc_gs = 0.f, acc_gc = 0.f, acc_mnum = 0.f, acc_mden = 0.f;

        #pragma unroll 1
        for (int it2 = 0; it2 < 4; ++it2) {
            float px=0.f, py=0.f, pz=0.f, tx=0.f, ty=0.f, tz=0.f;
            float m = 0.f, mnum = 0.f;
            if (av) {
                px = Pg[0]; py = Pg[1]; pz = Pg[2];
                tx = Tg[0]; ty = Tg[1]; tz = Tg[2];
                m = (*Ag != 0u) ? 1.f : 0.f;
                float dx = px - tx, dy = py - ty, dz = pz - tz;
                mnum = m * (dx*dx + dy*dy + dz*dz) * (1.f/3.f);
                if (m == 0.f) tx += 1e3f + 48.f * (float)a;
            }
            Pg += 2 * A * 3; Tg += 2 * A * 3; Ag += 2 * A;
            const unsigned int bal = __ballot_sync(FULLMASK, av && m != 0.f);
            float pw = px*px + py*py + pz*pz;
            float tw = tx*tx + ty*ty + tz*tz;

            // packed atom state
            const u64 cx = f2x_pack(px, tx), cy = f2x_pack(py, ty),
                      cz = f2x_pack(pz, tz), cw = f2x_pack(pw, tw);
            const u64 mx = f2x_mul(cx, NEG2), my = f2x_mul(cy, NEG2), mz = f2x_mul(cz, NEG2);

            float num = 0.f, den = 0.f;
            int j = a;
            #pragma unroll
            for (int d = 1; d <= 7; ++d) {
                j = (j + 1 == A) ? 0 : j + 1;          // (a+d) mod 14
                int src = (lane & 16) | j;
                u64 qx = __shfl_sync(FULLMASK, cx, src);
                u64 qy = __shfl_sync(FULLMASK, cy, src);
                u64 qz = __shfl_sync(FULLMASK, cz, src);
                u64 qw = __shfl_sync(FULLMASK, cw, src);
                u64 acc = f2x_add(cw, qw);
                acc = f2x_fma(mx, qx, acc);
                acc = f2x_fma(my, qy, acc);
                acc = f2x_fma(mz, qz, acc);
                float psq, tsq;
                f2x_unpack(acc, psq, tsq);
                float pe = fmaxf(psq, EPSV);
                float v = (pe + tsq) - 2.f * fast_sqrt(pe * tsq);
                bool act = (d < 7) ? av : (a < 7);
                if (act && tsq <= CUT2) { num += v; den += 1.f; }
            }

            // reduce within each 16-lane segment: (num,den) packed, mnum scalar
            u64 nd = f2x_pack(num, den);
            #pragma unroll
            for (int s = 8; s > 0; s >>= 1) {
                nd    = f2x_add(nd, __shfl_down_sync(FULLMASK, nd, s, 16));
                mnum += __shfl_down_sync(FULLMASK, mnum, s, 16);
            }
            f2x_unpack(nd, num, den);
            float gs = 0.f, gc = 0.f;
            if (a == 0 && den > 0.f) { gs = num / den; gc = 1.f; }
            gs   += __shfl_down_sync(FULLMASK, gs,   16);
            gc   += __shfl_down_sync(FULLMASK, gc,   16);
            mnum += __shfl_down_sync(FULLMASK, mnum, 16);
            if (lane == 0) {
                acc_gs   += gs;
                acc_gc   += gc;
                acc_mnum += mnum;
                acc_mden += (float)__popc(bal);
            }
        }

        if (lane == 0) {
            atomicAdd(&bacc[0], acc_gs);
            atomicAdd(&bacc[1], acc_gc);
            atomicAdd(&bacc[2], acc_mnum);
            atomicAdd(&bacc[3], acc_mden);
        }
        __syncthreads();
        if (t < 4) atomicAdd(&g_slots[t][bid & (NSLOT - 1)], bacc[t]);
    }

    // ======================= last-block finalization =======================
    __threadfence();
    if (t == 0) s_islast = (atomicAdd(&g_ticket, 1u) == (unsigned)(GRID - 1)) ? 1u : 0u;
    __syncthreads();
    if (!s_islast) return;

    float lig = 0.f, ld = 0.f, has = 0.f;
    if (t < B) {
        float sev = __ldcg(&g_lig_se[t]);
        float cn  = __ldcg(&g_lig_cnt[t]);
        float nu  = __ldcg(&g_lig_num[t]);
        float de  = __ldcg(&g_lig_den[t]);
        lig = sev / (3.f * fmaxf(cn, 1.f));
        if (de > 0.f) { ld = nu / de; has = 1.f; }
    }
    #pragma unroll
    for (int s = 16; s > 0; s >>= 1) {
        lig += __shfl_down_sync(FULLMASK, lig, s);
        ld  += __shfl_down_sync(FULLMASK, ld,  s);
        has += __shfl_down_sync(FULLMASK, has, s);
    }
    if (lane == 0 && t < B) { fin[0][w] = lig; fin[1][w] = ld; fin[2][w] = has; }

    if (t < NSLOT) {
        float s0 = __ldcg(&g_slots[0][t]);
        float s1 = __ldcg(&g_slots[1][t]);
        float s2 = __ldcg(&g_slots[2][t]);
        float s3 = __ldcg(&g_slots[3][t]);
        #pragma unroll
        for (int s = 16; s > 0; s >>= 1) {
            s0 += __shfl_down_sync(FULLMASK, s0, s);
            s1 += __shfl_down_sync(FULLMASK, s1, s);
            s2 += __shfl_down_sync(FULLMASK, s2, s);
            s3 += __shfl_down_sync(FULLMASK, s3, s);
        }
        if (t == 0) { sl[0] = s0; sl[1] = s1; sl[2] = s2; sl[3] = s3; }
    }
    __syncthreads();

    // reset scratch for next graph replay
    if (t < B) {
        g_lig_num[t] = 0.f; g_lig_den[t] = 0.f;
        g_lig_se[t]  = 0.f; g_lig_cnt[t] = 0.f;
    }
    if (t < 4 * NSLOT) g_slots[t >> 5][t & (NSLOT - 1)] = 0.f;
    if (t == 1) g_ticket = 0u;

    if (t == 0) {
        float ligand_loss = (fin[0][0] + fin[0][1]) * (1.f / 64.f);
        float hs = fin[2][0] + fin[2][1];
        float ligand_dist = (fin[1][0] + fin[1][1]) / fmaxf(hs, 1.f);
        float sc  = sl[2] / fmaxf(sl[3], 1.f);
        float scd = sl[0] / fmaxf(sl[1], 1.f);
        float total = ligand_loss + 0.2f * ligand_dist + 0.5f * sc + 0.1f * scd;
        for (int k = 0; k < out_size; ++k) out[k] = total;
    }
}

extern "C" void kernel_launch(void* const* d_in, const int* in_sizes, int n_in,
                              void* d_out, int out_size) {
    const float* lp  = (const float*)d_in[0];
    const float* lt  = (const float*)d_in[1];
    const float* scp = (const float*)d_in[2];
    const float* sct = (const float*)d_in[3];
    const unsigned int* lm = (const unsigned int*)d_in[4];
    const unsigned int* am = (const unsigned int*)d_in[5];
    (void)in_sizes; (void)n_in;

    fused_kernel<<<GRID, 256>>>(lp, lt, scp, sct, lm, am, (float*)d_out, out_size);
}

// round 17
// speedup vs baseline: 1.1400x; 1.1400x over previous
#include <cuda_runtime.h>

#define FULLMASK 0xffffffffu

constexpr int B = 64;
constexpr int L = 512;
constexpr int R = 1024;
constexpr int A = 14;
constexpr float EPSV = 1e-12f;
constexpr float CUT2 = 25.0f;     // CUTOFF^2

constexpr int LIG_BLOCKS_PER_B = 4;                       // each does 7 off-diag + 2 diag tiles
constexpr int LIG_BLOCKS = B * LIG_BLOCKS_PER_B;          // 256
constexpr int SC_GROUPS_PER_BLOCK = 64;                   // 8 warps x 8 groups
constexpr int SC_BLOCKS = (B * R) / SC_GROUPS_PER_BLOCK;  // 1024
constexpr int GRID = LIG_BLOCKS + SC_BLOCKS;              // 1280
constexpr int NSLOT = 32;

// -------- persistent scratch (zeroed at load; finalizer re-zeros each run) --------
__device__ float g_lig_num[B];
__device__ float g_lig_den[B];
__device__ float g_lig_se[B];
__device__ float g_lig_cnt[B];
__device__ float g_slots[4][NSLOT];
__device__ unsigned int g_ticket;

// off-diagonal tile pair table: (a<<4)|b for 0<=a<b<8, 28 entries
__constant__ unsigned char c_tpairs[28] = {
    0x01,0x02,0x03,0x04,0x05,0x06,0x07,
    0x12,0x13,0x14,0x15,0x16,0x17,
    0x23,0x24,0x25,0x26,0x27,
    0x34,0x35,0x36,0x37,
    0x45,0x46,0x47,
    0x56,0x57,
    0x67
};

typedef unsigned long long u64;

__device__ __forceinline__ float fast_sqrt(float x) {
    float r;
    asm("sqrt.approx.f32 %0, %1;" : "=f"(r) : "f"(x));
    return r;
}
__device__ __forceinline__ u64 f2x_pack(float lo, float hi) {
    u64 r; asm("mov.b64 %0, {%1, %2};" : "=l"(r) : "f"(lo), "f"(hi)); return r;
}
__device__ __forceinline__ void f2x_unpack(u64 v, float& lo, float& hi) {
    asm("mov.b64 {%0, %1}, %2;" : "=f"(lo), "=f"(hi) : "l"(v));
}
__device__ __forceinline__ u64 f2x_add(u64 a, u64 b) {
    u64 r; asm("add.rn.f32x2 %0, %1, %2;" : "=l"(r) : "l"(a), "l"(b)); return r;
}
__device__ __forceinline__ u64 f2x_mul(u64 a, u64 b) {
    u64 r; asm("mul.rn.f32x2 %0, %1, %2;" : "=l"(r) : "l"(a), "l"(b)); return r;
}
__device__ __forceinline__ u64 f2x_fma(u64 a, u64 b, u64 c) {
    u64 r; asm("fma.rn.f32x2 %0, %1, %2, %3;" : "=l"(r) : "l"(a), "l"(b), "l"(c)); return r;
}

// packed epilogue: acc = (psq, tsq); accumulate (pd-td)^2 when tsq <= CUT2
// (tsq==0 impossible: i!=j structurally, masked targets pushed far apart)
__device__ __forceinline__ void pair_epi(u64 acc, float& num, float& den) {
    float psq, tsq;
    f2x_unpack(acc, psq, tsq);
    float pe = fmaxf(psq, EPSV);
    float v = (pe + tsq) - 2.f * fast_sqrt(pe * tsq);
    if (tsq <= CUT2) { num += v; den += 1.f; }
}

__global__ void __launch_bounds__(256, 5) fused_kernel(
    const float* __restrict__ lp, const float* __restrict__ lt,
    const float* __restrict__ scp, const float* __restrict__ sct,
    const unsigned int* __restrict__ lm, const unsigned int* __restrict__ am,
    float* __restrict__ out, int out_size)
{
    // packed layout: s_a[j] = (px, tx, py, ty), s_b[j] = (pz, tz, |p|^2, |t|^2)
    __shared__ float4 s_a[L];     // 8 KB
    __shared__ float4 s_b[L];     // 8 KB
    __shared__ float4 wr[8];
    __shared__ float bacc[4];
    __shared__ unsigned int s_islast;
    __shared__ float fin[3][2];
    __shared__ float sl[4];

    const int t = threadIdx.x;
    const int bid = blockIdx.x;
    const int lane = t & 31;
    const int w = t >> 5;
    const u64 NEG2 = f2x_pack(-2.f, -2.f);

    if (bid < LIG_BLOCKS) {
        // ======================= ligand (identical to the 29.2us R12 path) =======================
        const int b = bid >> 2;
        const int r = bid & 3;
        const float* P = lp + (size_t)b * L * 3;
        const float* T = lt + (size_t)b * L * 3;
        const unsigned int* M = lm + (size_t)b * L;

        float num = 0.f, den = 0.f, se = 0.f, cnt = 0.f;

        // fill all 512 points once (packed layout); r==0 also does the coord MSE
        for (int j = t; j < L; j += 256) {
            float px = P[j*3+0], py = P[j*3+1], pz = P[j*3+2];
            float tx = T[j*3+0], ty = T[j*3+1], tz = T[j*3+2];
            bool m = (M[j] != 0u);
            if (r == 0 && m) {
                float dx = px - tx, dy = py - ty, dz = pz - tz;
                se  += dx*dx + dy*dy + dz*dz;
                cnt += 1.f;
            }
            if (!m) tx += 1e4f + 64.f * (float)j;   // push invalid targets apart
            float pw = px*px + py*py + pz*pz;
            float tw = tx*tx + ty*ty + tz*tz;
            s_a[j] = make_float4(px, tx, py, ty);
            s_b[j] = make_float4(pz, tz, pw, tw);
        }
        __syncthreads();   // smem read-only from here on

        const ulonglong2* sa2 = (const ulonglong2*)s_a;
        const ulonglong2* sb2 = (const ulonglong2*)s_b;

        // ---- 7 off-diagonal 64x64 tile combos (2i x 8j, broadcast j, packed math) ----
        #pragma unroll 1
        for (int c = 7*r; c < 7*r + 7; ++c) {
            const int code = c_tpairs[c];
            const int ta = code >> 4, tb = code & 15;
            const int ia = ta*64 + lane;
            ulonglong2 a0 = sa2[ia],      b0 = sb2[ia];
            ulonglong2 a1 = sa2[ia + 32], b1 = sb2[ia + 32];
            const u64 ix0 = f2x_mul(a0.x, NEG2), iy0 = f2x_mul(a0.y, NEG2),
                      iz0 = f2x_mul(b0.x, NEG2), iw0 = b0.y;
            const u64 ix1 = f2x_mul(a1.x, NEG2), iy1 = f2x_mul(a1.y, NEG2),
                      iz1 = f2x_mul(b1.x, NEG2), iw1 = b1.y;
            const int jb = tb*64 + w;       // warp-uniform j -> broadcast LDS
            #pragma unroll
            for (int it = 0; it < 8; ++it) {
                ulonglong2 aj = sa2[jb + 8*it];
                ulonglong2 bj = sb2[jb + 8*it];
                u64 acc0 = f2x_add(iw0, bj.y);
                acc0 = f2x_fma(ix0, aj.x, acc0);
                acc0 = f2x_fma(iy0, aj.y, acc0);
                acc0 = f2x_fma(iz0, bj.x, acc0);
                pair_epi(acc0, num, den);
                u64 acc1 = f2x_add(iw1, bj.y);
                acc1 = f2x_fma(ix1, aj.x, acc1);
                acc1 = f2x_fma(iy1, aj.y, acc1);
                acc1 = f2x_fma(iz1, bj.x, acc1);
                pair_epi(acc1, num, den);
            }
        }

        // ---- 2 diagonal tiles: round-robin within 64 (packed math) ----
        #pragma unroll 1
        for (int dt_ = 2*r; dt_ < 2*r + 2; ++dt_) {
            const int base = dt_ * 64;
            const int il   = t & 63;
            const int off  = t >> 6;
            ulonglong2 ai = sa2[base + il], bi = sb2[base + il];
            const u64 ix = f2x_mul(ai.x, NEG2), iy = f2x_mul(ai.y, NEG2),
                      iz = f2x_mul(bi.x, NEG2), iw = bi.y;
            #pragma unroll
            for (int k = 1 + off; k <= 32; k += 4) {
                if (k == 32 && il >= 32) break;
                int j = base + ((il + k) & 63);
                ulonglong2 aj = sa2[j];
                ulonglong2 bj = sb2[j];
                u64 acc = f2x_add(iw, bj.y);
                acc = f2x_fma(ix, aj.x, acc);
                acc = f2x_fma(iy, aj.y, acc);
                acc = f2x_fma(iz, bj.x, acc);
                pair_epi(acc, num, den);
            }
        }

        // block reduce 4 vars -> per-batch atomics
        #pragma unroll
        for (int s = 16; s > 0; s >>= 1) {
            num += __shfl_down_sync(FULLMASK, num, s);
            den += __shfl_down_sync(FULLMASK, den, s);
            se  += __shfl_down_sync(FULLMASK, se,  s);
            cnt += __shfl_down_sync(FULLMASK, cnt, s);
        }
        if (lane == 0) wr[w] = make_float4(num, den, se, cnt);
        __syncthreads();
        if (t < 8) {
            float4 v4 = wr[t];
            float a0 = v4.x, a1 = v4.y, a2 = v4.z, a3 = v4.w;
            #pragma unroll
            for (int s = 4; s > 0; s >>= 1) {
                a0 += __shfl_down_sync(0xffu, a0, s);
                a1 += __shfl_down_sync(0xffu, a1, s);
                a2 += __shfl_down_sync(0xffu, a2, s);
                a3 += __shfl_down_sync(0xffu, a3, s);
            }
            if (t == 0) {
                atomicAdd(&g_lig_num[b], a0);
                atomicAdd(&g_lig_den[b], a1);
                atomicAdd(&g_lig_se[b],  a2);
                atomicAdd(&g_lig_cnt[b], a3);
            }
        }
    } else {
        // ======================= sidechain (diff-form, pre-negated shuffles) =======================
        if (t < 4) bacc[t] = 0.f;
        __syncthreads();

        const int h = (lane >> 4);          // half-warp id
        const int a = lane & 15;            // atom slot
        const bool av = a < A;
        const unsigned int g0 = (unsigned int)(bid - LIG_BLOCKS) * SC_GROUPS_PER_BLOCK + w * 8 + h;

        // base pointers computed once; advanced by constant strides per iteration
        const float* Pg = scp + (size_t)g0 * (A*3) + a*3;
        const float* Tg = sct + (size_t)g0 * (A*3) + a*3;
        const unsigned int* Ag = am + (size_t)g0 * A + a;

        float acc_gs = 0.f, acc_gc = 0.f, acc_mnum = 0.f, acc_mden = 0.f;

        #pragma unroll 1
        for (int it2 = 0; it2 < 4; ++it2) {
            float px=0.f, py=0.f, pz=0.f, tx=0.f, ty=0.f, tz=0.f;
            float m = 0.f, mnum = 0.f;
            if (av) {
                px = Pg[0]; py = Pg[1]; pz = Pg[2];
                tx = Tg[0]; ty = Tg[1]; tz = Tg[2];
                m = (*Ag != 0u) ? 1.f : 0.f;
                float dx = px - tx, dy = py - ty, dz = pz - tz;
                mnum = m * (dx*dx + dy*dy + dz*dz) * (1.f/3.f);
                if (m == 0.f) tx += 1e3f + 48.f * (float)a;
            }
            Pg += 2 * A * 3; Tg += 2 * A * 3; Ag += 2 * A;
            const unsigned int bal = __ballot_sync(FULLMASK, av && m != 0.f);

            // packed atom coords + pre-negated copies (for diff via add after shuffle)
            const u64 cx = f2x_pack(px, tx), cy = f2x_pack(py, ty), cz = f2x_pack(pz, tz);
            const u64 nx = f2x_pack(-px, -tx), ny = f2x_pack(-py, -ty), nz = f2x_pack(-pz, -tz);

            float num = 0.f, den = 0.f;
            int j = a;
            #pragma unroll
            for (int d = 1; d <= 7; ++d) {
                j = (j + 1 == A) ? 0 : j + 1;          // (a+d) mod 14
                int src = (lane & 16) | j;
                // d = c - q  via  c + shfl(-c)
                u64 dx2 = f2x_add(cx, __shfl_sync(FULLMASK, nx, src));
                u64 dy2 = f2x_add(cy, __shfl_sync(FULLMASK, ny, src));
                u64 dz2 = f2x_add(cz, __shfl_sync(FULLMASK, nz, src));
                u64 acc = f2x_mul(dx2, dx2);
                acc = f2x_fma(dy2, dy2, acc);
                acc = f2x_fma(dz2, dz2, acc);
                float psq, tsq;
                f2x_unpack(acc, psq, tsq);
                float pe = fmaxf(psq, EPSV);
                float v = (pe + tsq) - 2.f * fast_sqrt(pe * tsq);
                bool act = (d < 7) ? av : (a < 7);
                if (act && tsq <= CUT2) { num += v; den += 1.f; }
            }

            // reduce within each 16-lane segment: (num,den) packed, mnum scalar
            u64 nd = f2x_pack(num, den);
            #pragma unroll
            for (int s = 8; s > 0; s >>= 1) {
                nd    = f2x_add(nd, __shfl_down_sync(FULLMASK, nd, s, 16));
                mnum += __shfl_down_sync(FULLMASK, mnum, s, 16);
            }
            f2x_unpack(nd, num, den);
            float gs = 0.f, gc = 0.f;
            if (a == 0 && den > 0.f) { gs = num / den; gc = 1.f; }
            gs   += __shfl_down_sync(FULLMASK, gs,   16);
            gc   += __shfl_down_sync(FULLMASK, gc,   16);
            mnum += __shfl_down_sync(FULLMASK, mnum, 16);
            if (lane == 0) {
                acc_gs   += gs;
                acc_gc   += gc;
                acc_mnum += mnum;
                acc_mden += (float)__popc(bal);
            }
        }

        if (lane == 0) {
            atomicAdd(&bacc[0], acc_gs);
            atomicAdd(&bacc[1], acc_gc);
            atomicAdd(&bacc[2], acc_mnum);
            atomicAdd(&bacc[3], acc_mden);
        }
        __syncthreads();
        if (t < 4) atomicAdd(&g_slots[t][bid & (NSLOT - 1)], bacc[t]);
    }

    // ======================= last-block finalization =======================
    __threadfence();
    if (t == 0) s_islast = (atomicAdd(&g_ticket, 1u) == (unsigned)(GRID - 1)) ? 1u : 0u;
    __syncthreads();
    if (!s_islast) return;

    float lig = 0.f, ld = 0.f, has = 0.f;
    if (t < B) {
        float sev = __ldcg(&g_lig_se[t]);
        float cn  = __ldcg(&g_lig_cnt[t]);
        float nu  = __ldcg(&g_lig_num[t]);
        float de  = __ldcg(&g_lig_den[t]);
        lig = sev / (3.f * fmaxf(cn, 1.f));
        if (de > 0.f) { ld = nu / de; has = 1.f; }
    }
    #pragma unroll
    for (int s = 16; s > 0; s >>= 1) {
        lig += __shfl_down_sync(FULLMASK, lig, s);
        ld  += __shfl_down_sync(FULLMASK, ld,  s);
        has += __shfl_down_sync(FULLMASK, has, s);
    }
    if (lane == 0 && t < B) { fin[0][w] = lig; fin[1][w] = ld; fin[2][w] = has; }

    if (t < NSLOT) {
        float s0 = __ldcg(&g_slots[0][t]);
        float s1 = __ldcg(&g_slots[1][t]);
        float s2 = __ldcg(&g_slots[2][t]);
        float s3 = __ldcg(&g_slots[3][t]);
        #pragma unroll
        for (int s = 16; s > 0; s >>= 1) {
            s0 += __shfl_down_sync(FULLMASK, s0, s);
            s1 += __shfl_down_sync(FULLMASK, s1, s);
            s2 += __shfl_down_sync(FULLMASK, s2, s);
            s3 += __shfl_down_sync(FULLMASK, s3, s);
        }
        if (t == 0) { sl[0] = s0; sl[1] = s1; sl[2] = s2; sl[3] = s3; }
    }
    __syncthreads();

    // reset scratch for next graph replay
    if (t < B) {
        g_lig_num[t] = 0.f; g_lig_den[t] = 0.f;
        g_lig_se[t]  = 0.f; g_lig_cnt[t] = 0.f;
    }
    if (t < 4 * NSLOT) g_slots[t >> 5][t & (NSLOT - 1)] = 0.f;
    if (t == 1) g_ticket = 0u;

    if (t == 0) {
        float ligand_loss = (fin[0][0] + fin[0][1]) * (1.f / 64.f);
        float hs = fin[2][0] + fin[2][1];
        float ligand_dist = (fin[1][0] + fin[1][1]) / fmaxf(hs, 1.f);
        float sc  = sl[2] / fmaxf(sl[3], 1.f);
        float scd = sl[0] / fmaxf(sl[1], 1.f);
        float total = ligand_loss + 0.2f * ligand_dist + 0.5f * sc + 0.1f * scd;
        for (int k = 0; k < out_size; ++k) out[k] = total;
    }
}

extern "C" void kernel_launch(void* const* d_in, const int* in_sizes, int n_in,
                              void* d_out, int out_size) {
    const float* lp  = (const float*)d_in[0];
    const float* lt  = (const float*)d_in[1];
    const float* scp = (const float*)d_in[2];
    const float* sct = (const float*)d_in[3];
    const unsigned int* lm = (const unsigned int*)d_in[4];
    const unsigned int* am = (const unsigned int*)d_in[5];
    (void)in_sizes; (void)n_in;

    fused_kernel<<<GRID, 256>>>(lp, lt, scp, sct, lm, am, (float*)d_out, out_size);
}